// round 1
// baseline (speedup 1.0000x reference)
#include <cuda_runtime.h>
#include <cstdint>

// ---------------------------------------------------------------------------
// VQVAE forward, sm_103a.
//   inputs (metadata order): x[65536,1024] f32, W_enc[100,1024], b_enc[100],
//                            codebook[21,100], W_dec[1024,100], b_dec[1024]
//   outputs (flattened f32): x_recon[65536*1024], vq_loss[1], indices[65536]
//
// Plan:
//   K0 setup : recon_table[21][1024] = codebook@W_dec^T + b_dec ; cnorm[21] ; loss=0
//   K1 main  : z_e GEMM (fp32 via packed fma.rn.f32x2) + argmin + loss + idx
//   K2 gather: x_recon[i] = recon_table[idx[i]]
//   K3 fin   : write scalar loss
// ---------------------------------------------------------------------------

#define NCODES 21
#define LDIM   100
#define IDIM   1024

__device__ float  g_recon[NCODES * IDIM];
__device__ float  g_cnorm[NCODES];
__device__ int    g_idx[65536];
__device__ double g_loss;

__device__ __forceinline__ unsigned long long pack2(float x) {
    unsigned long long r;
    asm("mov.b64 %0, {%1, %1};" : "=l"(r) : "f"(x));
    return r;
}
__device__ __forceinline__ void fma2(unsigned long long& d,
                                     unsigned long long a,
                                     unsigned long long b) {
    asm("fma.rn.f32x2 %0, %1, %2, %0;" : "+l"(d) : "l"(a), "l"(b));
}
__device__ __forceinline__ float2 unpack2(unsigned long long v) {
    float2 f;
    asm("mov.b64 {%0, %1}, %2;" : "=f"(f.x), "=f"(f.y) : "l"(v));
    return f;
}

// ---------------------------------------------------------------------------
// K0: recon table (21x1024), code norms, loss reset
// ---------------------------------------------------------------------------
__global__ void vq_setup_kernel(const float* __restrict__ codebook,
                                const float* __restrict__ W_dec,
                                const float* __restrict__ b_dec) {
    int g = blockIdx.x * 256 + threadIdx.x;
    if (g < NCODES * IDIM) {
        int k = g >> 10;        // code
        int d = g & 1023;       // output dim
        const float* c = codebook + k * LDIM;
        const float* w = W_dec + (size_t)d * LDIM;
        float s = b_dec[d];
#pragma unroll 4
        for (int j = 0; j < LDIM; ++j) s += c[j] * w[j];
        g_recon[g] = s;
    }
    if (g < NCODES) {
        const float* c = codebook + g * LDIM;
        float s = 0.f;
#pragma unroll 4
        for (int j = 0; j < LDIM; ++j) s += c[j] * c[j];
        g_cnorm[g] = s;
    }
    if (g == 0) g_loss = 0.0;
}

// ---------------------------------------------------------------------------
// K1: main. Block = 64 rows x 128 cols (cols >= 100 padded w/ zero weights).
// 256 threads, thread tile 4 rows x 8 cols, K-chunk 32.
// ---------------------------------------------------------------------------
#define KC   32
#define XSS  68    // xs stride (k-major, [KC][64]) -- padded vs bank conflicts
#define WSS  132   // ws stride (k-major, [KC][128])
#define ZSS  104   // z_e tile stride ([64][100])
#define XW_W 2176  // ws offset inside sh (= KC*XSS)

__global__ __launch_bounds__(256, 2)
void vq_main_kernel(const float* __restrict__ x,
                    const float* __restrict__ W_enc,
                    const float* __restrict__ b_enc,
                    const float* __restrict__ codebook,
                    float* __restrict__ out_idx) {
    __shared__ __align__(16) float sh[6656];   // GEMM tiles, then z_e tile
    __shared__ float cbs[NCODES * LDIM];
    __shared__ float cns[NCODES];
    __shared__ float s_loss;

    const int t    = threadIdx.x;
    const int row0 = blockIdx.x * 64;

    for (int i = t; i < NCODES * LDIM; i += 256) cbs[i] = codebook[i];
    if (t < NCODES) cns[t] = g_cnorm[t];
    if (t == 0)     s_loss = 0.f;

    unsigned long long acc[4][4];
#pragma unroll
    for (int i = 0; i < 4; ++i)
#pragma unroll
        for (int j = 0; j < 4; ++j) acc[i][j] = 0ull;

    const int rg = t >> 4, cg = t & 15;
    const int r0 = rg * 4, c0 = cg * 8;

    for (int kc = 0; kc < IDIM; kc += KC) {
        __syncthreads();
        // ---- load x tile (64 rows x 32 k), store transposed xs[kk][row]
#pragma unroll
        for (int i = 0; i < 2; ++i) {
            int idx = i * 256 + t;                 // 0..511
            int r = idx >> 3, f = idx & 7;
            float4 v = *(const float4*)(x + (size_t)(row0 + r) * IDIM + kc + f * 4);
            sh[(f * 4 + 0) * XSS + r] = v.x;
            sh[(f * 4 + 1) * XSS + r] = v.y;
            sh[(f * 4 + 2) * XSS + r] = v.z;
            sh[(f * 4 + 3) * XSS + r] = v.w;
        }
        // ---- load W tile (128 cols x 32 k, cols>=100 zero), transposed ws[kk][col]
#pragma unroll
        for (int i = 0; i < 4; ++i) {
            int idx = i * 256 + t;                 // 0..1023
            int c = idx >> 3, f = idx & 7;
            float4 v = make_float4(0.f, 0.f, 0.f, 0.f);
            if (c < LDIM)
                v = *(const float4*)(W_enc + (size_t)c * IDIM + kc + f * 4);
            sh[XW_W + (f * 4 + 0) * WSS + c] = v.x;
            sh[XW_W + (f * 4 + 1) * WSS + c] = v.y;
            sh[XW_W + (f * 4 + 2) * WSS + c] = v.z;
            sh[XW_W + (f * 4 + 3) * WSS + c] = v.w;
        }
        __syncthreads();
        // ---- compute: 16 packed FFMA2 per kk
#pragma unroll 8
        for (int kk = 0; kk < KC; ++kk) {
            float4 av = *(const float4*)&sh[kk * XSS + r0];
            ulonglong2 b0 = *(const ulonglong2*)&sh[XW_W + kk * WSS + c0];
            ulonglong2 b1 = *(const ulonglong2*)&sh[XW_W + kk * WSS + c0 + 4];
            unsigned long long a;
            a = pack2(av.x);
            fma2(acc[0][0], a, b0.x); fma2(acc[0][1], a, b0.y);
            fma2(acc[0][2], a, b1.x); fma2(acc[0][3], a, b1.y);
            a = pack2(av.y);
            fma2(acc[1][0], a, b0.x); fma2(acc[1][1], a, b0.y);
            fma2(acc[1][2], a, b1.x); fma2(acc[1][3], a, b1.y);
            a = pack2(av.z);
            fma2(acc[2][0], a, b0.x); fma2(acc[2][1], a, b0.y);
            fma2(acc[2][2], a, b1.x); fma2(acc[2][3], a, b1.y);
            a = pack2(av.w);
            fma2(acc[3][0], a, b0.x); fma2(acc[3][1], a, b0.y);
            fma2(acc[3][2], a, b1.x); fma2(acc[3][3], a, b1.y);
        }
    }
    __syncthreads();

    // ---- epilogue: add bias, stash z_e tile in sh ([64][100], stride 104)
#pragma unroll
    for (int r = 0; r < 4; ++r) {
#pragma unroll
        for (int j = 0; j < 4; ++j) {
            float2 f = unpack2(acc[r][j]);
            int c = c0 + j * 2;
            if (c < LDIM)     sh[(r0 + r) * ZSS + c]     = f.x + b_enc[c];
            if (c + 1 < LDIM) sh[(r0 + r) * ZSS + c + 1] = f.y + b_enc[c + 1];
        }
    }
    __syncthreads();

    // ---- argmin + loss: 4 threads per row
    const int row = t >> 2, h = t & 3;
    const float* z = &sh[row * ZSS];

    float zz = 0.f;
#pragma unroll 4
    for (int j = 0; j < LDIM; ++j) { float v = z[j]; zz += v * v; }

    float best_d = 3.4e38f, best_dot = 0.f;
    int best_k = 1 << 30;
    for (int k = h; k < NCODES; k += 4) {
        const float* c = &cbs[k * LDIM];
        float dot = 0.f;
#pragma unroll 4
        for (int j = 0; j < LDIM; ++j) dot += z[j] * c[j];
        float d = cns[k] - 2.f * dot;        // ||z||^2 omitted: constant per row
        if (d < best_d) { best_d = d; best_k = k; best_dot = dot; }
    }
    // reduce across the 4 threads of this row; first-min tie-break (smaller k)
#pragma unroll
    for (int off = 1; off < 4; off <<= 1) {
        float od  = __shfl_xor_sync(0xffffffffu, best_d, off);
        int   ok  = __shfl_xor_sync(0xffffffffu, best_k, off);
        float odt = __shfl_xor_sync(0xffffffffu, best_dot, off);
        if (od < best_d || (od == best_d && ok < best_k)) {
            best_d = od; best_k = ok; best_dot = odt;
        }
    }
    if (h == 0) {
        int grow = row0 + row;
        g_idx[grow]   = best_k;
        out_idx[grow] = (float)best_k;
        float lr = zz - 2.f * best_dot + cns[best_k];   // sum_j (z-c)^2
        atomicAdd(&s_loss, lr);
    }
    __syncthreads();
    if (t == 0) atomicAdd(&g_loss, (double)s_loss);
}

// ---------------------------------------------------------------------------
// K2: gather recon rows (store-bound, float4 coalesced)
// ---------------------------------------------------------------------------
__global__ void vq_gather_kernel(float* __restrict__ out) {
    int row = blockIdx.x * 8;
#pragma unroll
    for (int r = 0; r < 8; ++r) {
        int k = g_idx[row + r];
        const float4* s = (const float4*)(g_recon + (size_t)k * IDIM);
        float4*       d = (float4*)(out + (size_t)(row + r) * IDIM);
        d[threadIdx.x] = s[threadIdx.x];
    }
}

// ---------------------------------------------------------------------------
// K3: finalize scalar loss: 1.1 * mean
// ---------------------------------------------------------------------------
__global__ void vq_fin_kernel(float* __restrict__ out_loss, int M) {
    out_loss[0] = (float)(1.1 * g_loss / ((double)M * (double)LDIM));
}

extern "C" void kernel_launch(void* const* d_in, const int* in_sizes, int n_in,
                              void* d_out, int out_size) {
    const float* x        = (const float*)d_in[0];
    const float* W_enc    = (const float*)d_in[1];
    const float* b_enc    = (const float*)d_in[2];
    const float* codebook = (const float*)d_in[3];
    const float* W_dec    = (const float*)d_in[4];
    const float* b_dec    = (const float*)d_in[5];
    float* out = (float*)d_out;

    const int M = in_sizes[0] / IDIM;          // 65536
    float* out_recon = out;                    // M*1024
    float* out_loss  = out + (size_t)M * IDIM; // 1
    float* out_idx   = out_loss + 1;           // M

    vq_setup_kernel<<<(NCODES * IDIM + 255) / 256, 256>>>(codebook, W_dec, b_dec);
    vq_main_kernel<<<M / 64, 256>>>(x, W_enc, b_enc, codebook, out_idx);
    vq_gather_kernel<<<M / 8, 256>>>(out_recon);
    vq_fin_kernel<<<1, 1>>>(out_loss, M);
}

// round 7
// speedup vs baseline: 2.7068x; 2.7068x over previous
#include <cuda_runtime.h>
#include <cuda_bf16.h>
#include <cstdint>

// ---------------------------------------------------------------------------
// VQVAE forward on sm_103 (baseline PTX: ldmatrix + mma.sync bf16).
//   z_e = x @ W_enc^T + b_enc   via 3-way bf16 split HMMA (fp32 accum)
//     - z columns   (0..99)  : 3 products  (hh + hm + mh)   ~3*2^-16 err
//     - dot columns (100..120): 6 products (+hl + lh + mm)  ~2^-24  err
//   argmin / loss  : in-register epilogue + quad shfl reduce
//   x_recon        : fused coalesced gather from precomputed 21x1024 table
// ---------------------------------------------------------------------------

#define NCODES 21
#define LDIM   100
#define IDIM   1024
#define NPAD   128
#define CTA_M  128
#define KC     64
#define NCHUNK (IDIM / KC)
#define NT     16

__device__ __nv_bfloat16 g_Bh[NPAD * IDIM];
__device__ __nv_bfloat16 g_Bm[NPAD * IDIM];
__device__ __nv_bfloat16 g_Bl[NPAD * IDIM];
__device__ float  g_recon[NCODES * IDIM];
__device__ float  g_ck[NCODES];            // ||c_k||^2 - 2 b.c_k
__device__ double g_loss;

__device__ __forceinline__ uint32_t smem_u32(const void* p) {
    uint32_t a;
    asm("{ .reg .u64 t; cvta.to.shared.u64 t, %1; cvt.u32.u64 %0, t; }"
        : "=r"(a) : "l"(p));
    return a;
}
__device__ __forceinline__ uint32_t pack_bf16x2_rn(float a, float b) {
    uint32_t r;   // low 16 = a, high 16 = b
    asm("cvt.rn.bf16x2.f32 %0, %1, %2;" : "=r"(r) : "f"(b), "f"(a));
    return r;
}
__device__ __forceinline__ float lo_f(uint32_t p) { return __uint_as_float(p << 16); }
__device__ __forceinline__ float hi_f(uint32_t p) { return __uint_as_float(p & 0xffff0000u); }
__device__ __forceinline__ uint32_t swz(uint32_t o) { return o ^ ((o >> 3) & 0x70u); }

__device__ __forceinline__ void ldsm_x4(uint32_t* r, uint32_t addr) {
    asm volatile("ldmatrix.sync.aligned.m8n8.x4.shared.b16 {%0,%1,%2,%3}, [%4];"
                 : "=r"(r[0]), "=r"(r[1]), "=r"(r[2]), "=r"(r[3]) : "r"(addr));
}
__device__ __forceinline__ void ldsm_x2(uint32_t* r, uint32_t addr) {
    asm volatile("ldmatrix.sync.aligned.m8n8.x2.shared.b16 {%0,%1}, [%2];"
                 : "=r"(r[0]), "=r"(r[1]) : "r"(addr));
}
__device__ __forceinline__ void mma_bf16(float* d, const uint32_t* a, const uint32_t* b) {
    asm volatile("mma.sync.aligned.m16n8k16.row.col.f32.bf16.bf16.f32 "
                 "{%0,%1,%2,%3}, {%4,%5,%6,%7}, {%8,%9}, {%0,%1,%2,%3};"
                 : "+f"(d[0]), "+f"(d[1]), "+f"(d[2]), "+f"(d[3])
                 : "r"(a[0]), "r"(a[1]), "r"(a[2]), "r"(a[3]),
                   "r"(b[0]), "r"(b[1]));
}

// ---------------- smem layout (byte offsets from 128-aligned base) ----------
#define OFF_AH   0
#define OFF_AM   16384
#define OFF_AL   32768
#define OFF_BH   49152
#define OFF_BM   65536
#define OFF_BL   81920
#define OFF_BES  98304
#define OFF_CK   98816
#define OFF_SIDX 98912
#define OFF_LOSS 99424
#define SMEM_BYTES (99440 + 128)

// ---------------------------------------------------------------------------
// K0: setup — extended B (W_enc rows + cb@W_enc rows) 3-way RN split,
//             recon table, ck consts, loss reset
// ---------------------------------------------------------------------------
__global__ void vq_setup_kernel(const float* __restrict__ W_enc,
                                const float* __restrict__ b_enc,
                                const float* __restrict__ codebook,
                                const float* __restrict__ W_dec,
                                const float* __restrict__ b_dec) {
    int g = blockIdx.x * 256 + threadIdx.x;            // 0 .. 131071
    {
        int n = g >> 10, k = g & 1023;
        float w = 0.f;
        if (n < LDIM) {
            w = W_enc[n * IDIM + k];
        } else if (n < LDIM + NCODES) {
            const float* cb = codebook + (n - LDIM) * LDIM;
#pragma unroll 4
            for (int j = 0; j < LDIM; ++j) w += cb[j] * W_enc[j * IDIM + k];
        }
        __nv_bfloat16 h = __float2bfloat16_rn(w);
        float r1 = w - __bfloat162float(h);
        __nv_bfloat16 m = __float2bfloat16_rn(r1);
        float r2 = r1 - __bfloat162float(m);
        g_Bh[g] = h;
        g_Bm[g] = m;
        g_Bl[g] = __float2bfloat16_rn(r2);
    }
    if (g < NCODES * IDIM) {
        int k = g >> 10, d = g & 1023;
        const float* c = codebook + k * LDIM;
        const float* w = W_dec + (size_t)d * LDIM;
        float s = b_dec[d];
#pragma unroll 4
        for (int j = 0; j < LDIM; ++j) s += c[j] * w[j];
        g_recon[g] = s;
    }
    if (g < NCODES) {
        const float* c = codebook + g * LDIM;
        float cn = 0.f, bk = 0.f;
#pragma unroll 4
        for (int j = 0; j < LDIM; ++j) { cn += c[j] * c[j]; bk += b_enc[j] * c[j]; }
        g_ck[g] = cn - 2.f * bk;
    }
    if (g == 0) g_loss = 0.0;
}

// ---------------------------------------------------------------------------
// K1: main — HMMA 3-way-split GEMM + fused argmin/loss/recon
// ---------------------------------------------------------------------------
extern __shared__ __align__(16) char dsm_raw[];

__global__ __launch_bounds__(256, 2)
void vq_main_kernel(const float* __restrict__ x,
                    const float* __restrict__ b_enc,
                    float* __restrict__ out_recon,
                    float* __restrict__ out_idx) {
    const int t = threadIdx.x;
    const int w = t >> 5, L = t & 31;
    const int row0 = blockIdx.x * CTA_M;

    uint32_t raw  = smem_u32(dsm_raw);
    uint32_t base = (raw + 127u) & ~127u;
    char* sm = dsm_raw + (base - raw);

    char* Ah = sm + OFF_AH;  char* Am = sm + OFF_AM;  char* Al = sm + OFF_AL;
    char* Bh = sm + OFF_BH;  char* Bm = sm + OFF_BM;  char* Bl = sm + OFF_BL;
    float* bes   = (float*)(sm + OFF_BES);
    float* cks   = (float*)(sm + OFF_CK);
    int*   sidx  = (int*)  (sm + OFF_SIDX);
    float* sloss = (float*)(sm + OFF_LOSS);

    if (t < LDIM)   bes[t] = b_enc[t];
    if (t < NCODES) cks[t] = g_ck[t];
    if (t == 0)     *sloss = 0.f;

    float acc[NT][4];
#pragma unroll
    for (int j = 0; j < NT; ++j)
#pragma unroll
        for (int e = 0; e < 4; ++e) acc[j][e] = 0.f;

    const uint32_t mask  = (uint32_t)(L & 7) << 4;
    const uint32_t lowA0 = ((uint32_t)(L & 7) << 7) + ((uint32_t)(L >> 4) << 4);
    const uint32_t lowB0 = ((uint32_t)(L & 7) << 7) + ((uint32_t)((L >> 3) & 1) << 4);
    const uint32_t aRow  = ((uint32_t)(w * 2 + ((L >> 3) & 1))) << 10;
    const uint32_t AhB = base + OFF_AH + aRow;
    const uint32_t AmB = base + OFF_AM + aRow;
    const uint32_t AlB = base + OFF_AL + aRow;
    const uint32_t BhB = base + OFF_BH, BmB = base + OFF_BM, BlB = base + OFF_BL;

    for (int ch = 0; ch < NCHUNK; ++ch) {
        const int kc = ch * KC;
        __syncthreads();
        // ---- convert A: x fp32 -> (hi,mid,lo) bf16 RN splits, SW128 tiles
#pragma unroll
        for (int it = 0; it < 8; ++it) {
            int row = it * 16 + (t >> 4);
            int c4  = (t & 15) * 4;
            float4 v = *(const float4*)(x + (size_t)(row0 + row) * IDIM + kc + c4);

            uint32_t h01 = pack_bf16x2_rn(v.x, v.y);
            uint32_t h23 = pack_bf16x2_rn(v.z, v.w);
            float rx = v.x - lo_f(h01), ry = v.y - hi_f(h01);
            float rz = v.z - lo_f(h23), rw = v.w - hi_f(h23);
            uint32_t m01 = pack_bf16x2_rn(rx, ry);
            uint32_t m23 = pack_bf16x2_rn(rz, rw);
            uint32_t l01 = pack_bf16x2_rn(rx - lo_f(m01), ry - hi_f(m01));
            uint32_t l23 = pack_bf16x2_rn(rz - lo_f(m23), rw - hi_f(m23));

            uint32_t off = swz((uint32_t)(row * 128 + c4 * 2));
            *(uint2*)(Ah + off) = make_uint2(h01, h23);
            *(uint2*)(Am + off) = make_uint2(m01, m23);
            *(uint2*)(Al + off) = make_uint2(l01, l23);
        }
        // ---- stage B tiles (precomputed split, L2-hot)
#pragma unroll
        for (int it = 0; it < 4; ++it) {
            int idx = it * 256 + t;                 // 0..1023
            int n = idx >> 3, k8 = (idx & 7) * 8;
            uint32_t off = swz((uint32_t)(n * 128 + k8 * 2));
            size_t gsrc = (size_t)n * IDIM + kc + k8;
            *(uint4*)(Bh + off) = *(const uint4*)(g_Bh + gsrc);
            *(uint4*)(Bm + off) = *(const uint4*)(g_Bm + gsrc);
            *(uint4*)(Bl + off) = *(const uint4*)(g_Bl + gsrc);
        }
        __syncthreads();

#pragma unroll
        for (int ks = 0; ks < 4; ++ks) {
            const uint32_t aoff = (lowA0 + (ks << 5)) ^ mask;
            const uint32_t boff = (lowB0 + (ks << 5)) ^ mask;
            uint32_t ah[4], am[4], al[4];
            ldsm_x4(ah, AhB + aoff);
            ldsm_x4(am, AmB + aoff);
            ldsm_x4(al, AlB + aoff);
#pragma unroll
            for (int j = 0; j < NT; ++j) {
                uint32_t bh[2], bm[2];
                ldsm_x2(bh, BhB + boff + (j << 10));
                ldsm_x2(bm, BmB + boff + (j << 10));
                mma_bf16(acc[j], ah, bh);
                mma_bf16(acc[j], ah, bm);
                mma_bf16(acc[j], am, bh);
                if (j >= 12) {          // dot columns: full 2^-24 path
                    uint32_t bl[2];
                    ldsm_x2(bl, BlB + boff + (j << 10));
                    mma_bf16(acc[j], ah, bl);
                    mma_bf16(acc[j], al, bh);
                    mma_bf16(acc[j], am, bm);
                }
            }
        }
    }

    // ---- epilogue (registers only). Thread owns rows (w*16+q, +8),
    //      cols 8j + 2*c0 + e, with c0 = L&3, q = L>>2.
    const int c0 = L & 3;
    float zz0 = 0.f, zz1 = 0.f;
#pragma unroll
    for (int j = 0; j < 13; ++j) {
#pragma unroll
        for (int e = 0; e < 2; ++e) {
            int col = 8 * j + 2 * c0 + e;
            if (col < LDIM) {
                float b = bes[col];
                float z0 = acc[j][e]     + b;  zz0 += z0 * z0;
                float z1 = acc[j][e + 2] + b;  zz1 += z1 * z1;
            }
        }
    }
    float bd0 = 3.4e38f, bd1 = 3.4e38f;
    int   bk0 = NCODES,  bk1 = NCODES;
#pragma unroll
    for (int j = 12; j < NT; ++j) {
#pragma unroll
        for (int e = 0; e < 2; ++e) {
            int col = 8 * j + 2 * c0 + e;
            int k = col - LDIM;
            if (k >= 0 && k < NCODES) {
                float ckv = cks[k];
                float s0 = ckv - 2.f * acc[j][e];
                float s1 = ckv - 2.f * acc[j][e + 2];
                if (s0 < bd0) { bd0 = s0; bk0 = k; }
                if (s1 < bd1) { bd1 = s1; bk1 = k; }
            }
        }
    }
#pragma unroll
    for (int off = 1; off < 4; off <<= 1) {
        float od0 = __shfl_xor_sync(0xffffffffu, bd0, off);
        int   ok0 = __shfl_xor_sync(0xffffffffu, bk0, off);
        float od1 = __shfl_xor_sync(0xffffffffu, bd1, off);
        int   ok1 = __shfl_xor_sync(0xffffffffu, bk1, off);
        zz0 += __shfl_xor_sync(0xffffffffu, zz0, off);
        zz1 += __shfl_xor_sync(0xffffffffu, zz1, off);
        if (od0 < bd0 || (od0 == bd0 && ok0 < bk0)) { bd0 = od0; bk0 = ok0; }
        if (od1 < bd1 || (od1 == bd1 && ok1 < bk1)) { bd1 = od1; bk1 = ok1; }
    }
    if (c0 == 0) {
        int q  = L >> 2;
        int r0 = w * 16 + q, r1 = r0 + 8;
        sidx[r0] = bk0;  sidx[r1] = bk1;
        out_idx[row0 + r0] = (float)bk0;
        out_idx[row0 + r1] = (float)bk1;
        atomicAdd(sloss, (zz0 + bd0) + (zz1 + bd1));
    }
    __syncthreads();
    if (t == 0) atomicAdd(&g_loss, (double)*sloss);

    // ---- fused recon gather (table L2-resident)
#pragma unroll 4
    for (int r = 0; r < CTA_M; ++r) {
        int k = sidx[r];
        float4 v = *(const float4*)(g_recon + (size_t)k * IDIM + t * 4);
        *(float4*)(out_recon + (size_t)(row0 + r) * IDIM + t * 4) = v;
    }
}

// ---------------------------------------------------------------------------
// K2: finalize loss
// ---------------------------------------------------------------------------
__global__ void vq_fin_kernel(float* __restrict__ out_loss, int M) {
    out_loss[0] = (float)(1.1 * g_loss / ((double)M * (double)LDIM));
}

extern "C" void kernel_launch(void* const* d_in, const int* in_sizes, int n_in,
                              void* d_out, int out_size) {
    const float* x        = (const float*)d_in[0];
    const float* W_enc    = (const float*)d_in[1];
    const float* b_enc    = (const float*)d_in[2];
    const float* codebook = (const float*)d_in[3];
    const float* W_dec    = (const float*)d_in[4];
    const float* b_dec    = (const float*)d_in[5];
    float* out = (float*)d_out;

    const int M = in_sizes[0] / IDIM;           // 65536
    float* out_recon = out;
    float* out_loss  = out + (size_t)M * IDIM;
    float* out_idx   = out_loss + 1;

    cudaFuncSetAttribute(vq_main_kernel,
                         cudaFuncAttributeMaxDynamicSharedMemorySize, SMEM_BYTES);

    vq_setup_kernel<<<(NPAD * IDIM) / 256, 256>>>(W_enc, b_enc, codebook, W_dec, b_dec);
    vq_main_kernel<<<M / CTA_M, 256, SMEM_BYTES>>>(x, b_enc, out_recon, out_idx);
    vq_fin_kernel<<<1, 1>>>(out_loss, M);
}

// round 8
// speedup vs baseline: 3.3656x; 1.2434x over previous
#include <cuda_runtime.h>
#include <cuda_fp16.h>
#include <cstdint>

// ---------------------------------------------------------------------------
// VQVAE forward on sm_103 (baseline PTX: ldmatrix + mma.sync fp16).
//   z_e = x @ W_enc^T + b_enc  via scaled 2-way fp16 split HMMA (fp32 accum)
//     A scaled 2^8, B scaled 2^10 -> all split residuals stay fp16-normal.
//     z cols (0..99): 3 products (hh+hl+lh), ~2^-22 err
//     dot cols (100..120): 4 products (+ll), fp32-limited
//   argmin / loss  : in-register epilogue + quad shfl reduce
//   x_recon        : fused coalesced gather from precomputed 21x1024 table
// ---------------------------------------------------------------------------

#define NCODES 21
#define LDIM   100
#define IDIM   1024
#define NPAD   128
#define CTA_M  128
#define KC     64
#define NCHUNK (IDIM / KC)
#define NT     16

#define ASCALE 256.0f           // 2^8
#define BSCALE 1024.0f          // 2^10
#define INVS   3.814697265625e-06f   // 2^-18

__device__ __half g_Bh[NPAD * IDIM];
__device__ __half g_Bl[NPAD * IDIM];
__device__ float  g_recon[NCODES * IDIM];
__device__ float  g_ck[NCODES];            // ||c_k||^2 - 2 b.c_k
__device__ double g_loss;

__device__ __forceinline__ uint32_t smem_u32(const void* p) {
    uint32_t a;
    asm("{ .reg .u64 t; cvta.to.shared.u64 t, %1; cvt.u32.u64 %0, t; }"
        : "=r"(a) : "l"(p));
    return a;
}
__device__ __forceinline__ uint32_t pack_f16x2(float a, float b) {
    uint32_t r;   // low 16 = a, high 16 = b
    asm("cvt.rn.f16x2.f32 %0, %1, %2;" : "=r"(r) : "f"(b), "f"(a));
    return r;
}
__device__ __forceinline__ float2 unpack_h2(uint32_t p) {
    __half2 h = *reinterpret_cast<__half2*>(&p);
    return __half22float2(h);
}
__device__ __forceinline__ uint32_t swz(uint32_t o) { return o ^ ((o >> 3) & 0x70u); }

__device__ __forceinline__ void ldsm_x4(uint32_t* r, uint32_t addr) {
    asm volatile("ldmatrix.sync.aligned.m8n8.x4.shared.b16 {%0,%1,%2,%3}, [%4];"
                 : "=r"(r[0]), "=r"(r[1]), "=r"(r[2]), "=r"(r[3]) : "r"(addr));
}
__device__ __forceinline__ void mma_f16(float* d, const uint32_t* a, const uint32_t* b) {
    asm volatile("mma.sync.aligned.m16n8k16.row.col.f32.f16.f16.f32 "
                 "{%0,%1,%2,%3}, {%4,%5,%6,%7}, {%8,%9}, {%0,%1,%2,%3};"
                 : "+f"(d[0]), "+f"(d[1]), "+f"(d[2]), "+f"(d[3])
                 : "r"(a[0]), "r"(a[1]), "r"(a[2]), "r"(a[3]),
                   "r"(b[0]), "r"(b[1]));
}

// ---------------- smem layout (byte offsets from 128-aligned base) ----------
#define OFF_AH   0
#define OFF_AL   16384
#define OFF_BH   32768
#define OFF_BL   49152
#define OFF_BES  65536
#define OFF_CK   66048
#define OFF_SIDX 66176
#define OFF_LOSS 66688
#define SMEM_BYTES (66704 + 128)

// ---------------------------------------------------------------------------
// K0: setup — extended B (W_enc rows + cb@W_enc rows) scaled fp16 split,
//             recon table, ck consts, loss reset
// ---------------------------------------------------------------------------
__global__ void vq_setup_kernel(const float* __restrict__ W_enc,
                                const float* __restrict__ b_enc,
                                const float* __restrict__ codebook,
                                const float* __restrict__ W_dec,
                                const float* __restrict__ b_dec) {
    int g = blockIdx.x * 256 + threadIdx.x;            // 0 .. 131071
    {
        int n = g >> 10, k = g & 1023;
        float w = 0.f;
        if (n < LDIM) {
            w = W_enc[n * IDIM + k];
        } else if (n < LDIM + NCODES) {
            const float* cb = codebook + (n - LDIM) * LDIM;
#pragma unroll 20
            for (int j = 0; j < LDIM; ++j) w += cb[j] * W_enc[j * IDIM + k];
        }
        float ws = w * BSCALE;
        __half h = __float2half_rn(ws);
        g_Bh[g] = h;
        g_Bl[g] = __float2half_rn(ws - __half2float(h));
    }
    if (g < NCODES * IDIM) {
        int k = g >> 10, d = g & 1023;
        const float4* c4 = (const float4*)(codebook + k * LDIM);
        const float4* w4 = (const float4*)(W_dec + (size_t)d * LDIM);
        float s = b_dec[d];
#pragma unroll
        for (int j = 0; j < LDIM / 4; ++j) {
            float4 a = c4[j], b = w4[j];
            s += a.x * b.x + a.y * b.y + a.z * b.z + a.w * b.w;
        }
        g_recon[g] = s;
    }
    if (g < NCODES) {
        const float* c = codebook + g * LDIM;
        float cn = 0.f, bk = 0.f;
#pragma unroll 10
        for (int j = 0; j < LDIM; ++j) { cn += c[j] * c[j]; bk += b_enc[j] * c[j]; }
        g_ck[g] = cn - 2.f * bk;
    }
    if (g == 0) g_loss = 0.0;
}

// ---------------------------------------------------------------------------
// K1: main — HMMA scaled-fp16-split GEMM + fused argmin/loss/recon
// ---------------------------------------------------------------------------
extern __shared__ __align__(16) char dsm_raw[];

__global__ __launch_bounds__(256, 2)
void vq_main_kernel(const float* __restrict__ x,
                    const float* __restrict__ b_enc,
                    float* __restrict__ out_recon,
                    float* __restrict__ out_idx) {
    const int t = threadIdx.x;
    const int w = t >> 5, L = t & 31;
    const int row0 = blockIdx.x * CTA_M;

    uint32_t raw  = smem_u32(dsm_raw);
    uint32_t base = (raw + 127u) & ~127u;
    char* sm = dsm_raw + (base - raw);

    char* Ah = sm + OFF_AH;  char* Al = sm + OFF_AL;
    char* Bh = sm + OFF_BH;  char* Bl = sm + OFF_BL;
    float* bes   = (float*)(sm + OFF_BES);
    float* cks   = (float*)(sm + OFF_CK);
    int*   sidx  = (int*)  (sm + OFF_SIDX);
    float* sloss = (float*)(sm + OFF_LOSS);

    if (t < LDIM)   bes[t] = b_enc[t];
    if (t < NCODES) cks[t] = g_ck[t];
    if (t == 0)     *sloss = 0.f;

    float acc[NT][4];
#pragma unroll
    for (int j = 0; j < NT; ++j)
#pragma unroll
        for (int e = 0; e < 4; ++e) acc[j][e] = 0.f;

    const uint32_t mask  = (uint32_t)(L & 7) << 4;
    const uint32_t lowA0 = ((uint32_t)(L & 7) << 7) + ((uint32_t)(L >> 4) << 4);
    const uint32_t lowB4 = ((uint32_t)(L & 7) << 7) + ((uint32_t)((L >> 3) & 1) << 4)
                         + ((uint32_t)(L >> 4) << 10);
    const uint32_t aRow  = ((uint32_t)(w * 2 + ((L >> 3) & 1))) << 10;
    const uint32_t AhB = base + OFF_AH + aRow;
    const uint32_t AlB = base + OFF_AL + aRow;
    const uint32_t BhB = base + OFF_BH, BlB = base + OFF_BL;

    for (int ch = 0; ch < NCHUNK; ++ch) {
        const int kc = ch * KC;
        __syncthreads();
        // ---- convert A: x fp32 -> scaled (hi,lo) fp16 RN split, SW128 tiles
#pragma unroll
        for (int it = 0; it < 8; ++it) {
            int row = it * 16 + (t >> 4);
            int c4  = (t & 15) * 4;
            float4 v = *(const float4*)(x + (size_t)(row0 + row) * IDIM + kc + c4);
            float sx = v.x * ASCALE, sy = v.y * ASCALE;
            float sz = v.z * ASCALE, sw = v.w * ASCALE;
            uint32_t h01 = pack_f16x2(sx, sy);
            uint32_t h23 = pack_f16x2(sz, sw);
            float2 b01 = unpack_h2(h01), b23 = unpack_h2(h23);
            uint32_t l01 = pack_f16x2(sx - b01.x, sy - b01.y);
            uint32_t l23 = pack_f16x2(sz - b23.x, sw - b23.y);
            uint32_t off = swz((uint32_t)(row * 128 + c4 * 2));
            *(uint2*)(Ah + off) = make_uint2(h01, h23);
            *(uint2*)(Al + off) = make_uint2(l01, l23);
        }
        // ---- stage B tiles (precomputed scaled split, L2-hot)
#pragma unroll
        for (int it = 0; it < 4; ++it) {
            int idx = it * 256 + t;                 // 0..1023
            int n = idx >> 3, k8 = (idx & 7) * 8;
            uint32_t off = swz((uint32_t)(n * 128 + k8 * 2));
            size_t gsrc = (size_t)n * IDIM + kc + k8;
            *(uint4*)(Bh + off) = *(const uint4*)(g_Bh + gsrc);
            *(uint4*)(Bl + off) = *(const uint4*)(g_Bl + gsrc);
        }
        __syncthreads();

#pragma unroll
        for (int ks = 0; ks < 4; ++ks) {
            const uint32_t aoff = (lowA0 + (ks << 5)) ^ mask;
            const uint32_t boff = (lowB4 + (ks << 5)) ^ mask;
            uint32_t ah[4], al[4];
            ldsm_x4(ah, AhB + aoff);
            ldsm_x4(al, AlB + aoff);
#pragma unroll
            for (int j = 0; j < NT; j += 2) {
                uint32_t bh[4], bl[4];
                ldsm_x4(bh, BhB + boff + (j << 10));
                ldsm_x4(bl, BlB + boff + (j << 10));
                mma_f16(acc[j],     ah, bh);
                mma_f16(acc[j],     ah, bl);
                mma_f16(acc[j],     al, bh);
                mma_f16(acc[j + 1], ah, bh + 2);
                mma_f16(acc[j + 1], ah, bl + 2);
                mma_f16(acc[j + 1], al, bh + 2);
                if (j >= 12) {          // dot columns: add ll for full precision
                    mma_f16(acc[j],     al, bl);
                    mma_f16(acc[j + 1], al, bl + 2);
                }
            }
        }
    }

    // ---- epilogue (registers only). Thread owns rows (w*16+q, +8),
    //      cols 8j + 2*c0 + e, with c0 = L&3, q = L>>2. acc scaled by 2^18.
    const int c0 = L & 3;
    float zz0 = 0.f, zz1 = 0.f;
#pragma unroll
    for (int j = 0; j < 13; ++j) {
#pragma unroll
        for (int e = 0; e < 2; ++e) {
            int col = 8 * j + 2 * c0 + e;
            if (col < LDIM) {
                float b = bes[col];
                float z0 = fmaf(acc[j][e],     INVS, b);  zz0 += z0 * z0;
                float z1 = fmaf(acc[j][e + 2], INVS, b);  zz1 += z1 * z1;
            }
        }
    }
    float bd0 = 3.4e38f, bd1 = 3.4e38f;
    int   bk0 = NCODES,  bk1 = NCODES;
#pragma unroll
    for (int j = 12; j < NT; ++j) {
#pragma unroll
        for (int e = 0; e < 2; ++e) {
            int col = 8 * j + 2 * c0 + e;
            int k = col - LDIM;
            if (k >= 0 && k < NCODES) {
                float ckv = cks[k];
                float s0 = fmaf(acc[j][e],     -2.f * INVS, ckv);
                float s1 = fmaf(acc[j][e + 2], -2.f * INVS, ckv);
                if (s0 < bd0) { bd0 = s0; bk0 = k; }
                if (s1 < bd1) { bd1 = s1; bk1 = k; }
            }
        }
    }
#pragma unroll
    for (int off = 1; off < 4; off <<= 1) {
        float od0 = __shfl_xor_sync(0xffffffffu, bd0, off);
        int   ok0 = __shfl_xor_sync(0xffffffffu, bk0, off);
        float od1 = __shfl_xor_sync(0xffffffffu, bd1, off);
        int   ok1 = __shfl_xor_sync(0xffffffffu, bk1, off);
        zz0 += __shfl_xor_sync(0xffffffffu, zz0, off);
        zz1 += __shfl_xor_sync(0xffffffffu, zz1, off);
        if (od0 < bd0 || (od0 == bd0 && ok0 < bk0)) { bd0 = od0; bk0 = ok0; }
        if (od1 < bd1 || (od1 == bd1 && ok1 < bk1)) { bd1 = od1; bk1 = ok1; }
    }
    if (c0 == 0) {
        int q  = L >> 2;
        int r0 = w * 16 + q, r1 = r0 + 8;
        sidx[r0] = bk0;  sidx[r1] = bk1;
        out_idx[row0 + r0] = (float)bk0;
        out_idx[row0 + r1] = (float)bk1;
        atomicAdd(sloss, (zz0 + bd0) + (zz1 + bd1));
    }
    __syncthreads();
    if (t == 0) atomicAdd(&g_loss, (double)*sloss);

    // ---- fused recon gather (table L2-resident)
#pragma unroll 4
    for (int r = 0; r < CTA_M; ++r) {
        int k = sidx[r];
        float4 v = *(const float4*)(g_recon + (size_t)k * IDIM + t * 4);
        *(float4*)(out_recon + (size_t)(row0 + r) * IDIM + t * 4) = v;
    }
}

// ---------------------------------------------------------------------------
// K2: finalize loss
// ---------------------------------------------------------------------------
__global__ void vq_fin_kernel(float* __restrict__ out_loss, int M) {
    out_loss[0] = (float)(1.1 * g_loss / ((double)M * (double)LDIM));
}

extern "C" void kernel_launch(void* const* d_in, const int* in_sizes, int n_in,
                              void* d_out, int out_size) {
    const float* x        = (const float*)d_in[0];
    const float* W_enc    = (const float*)d_in[1];
    const float* b_enc    = (const float*)d_in[2];
    const float* codebook = (const float*)d_in[3];
    const float* W_dec    = (const float*)d_in[4];
    const float* b_dec    = (const float*)d_in[5];
    float* out = (float*)d_out;

    const int M = in_sizes[0] / IDIM;           // 65536
    float* out_recon = out;
    float* out_loss  = out + (size_t)M * IDIM;
    float* out_idx   = out_loss + 1;

    cudaFuncSetAttribute(vq_main_kernel,
                         cudaFuncAttributeMaxDynamicSharedMemorySize, SMEM_BYTES);

    vq_setup_kernel<<<(NPAD * IDIM) / 256, 256>>>(W_enc, b_enc, codebook, W_dec, b_dec);
    vq_main_kernel<<<M / CTA_M, 256, SMEM_BYTES>>>(x, b_enc, out_recon, out_idx);
    vq_fin_kernel<<<1, 1>>>(out_loss, M);
}

// round 9
// speedup vs baseline: 3.8221x; 1.1356x over previous
#include <cuda_runtime.h>
#include <cuda_fp16.h>
#include <cstdint>

// ---------------------------------------------------------------------------
// VQVAE forward on sm_103 (baseline PTX: ldmatrix + mma.sync fp16).
//   z_e = x @ W_enc^T + b_enc  via scaled fp16-split HMMA (fp32 accum)
//     A scaled 2^8, B scaled 2^10 -> residuals stay fp16-normal.
//     z tiles   (cols  0.. 95): 2 products (hh + lh)        ~5e-5 abs err
//     dot tiles (cols 96..127): 3 products (hh + lh + hl)   fp32-level
//   argmin / loss  : in-register epilogue + quad shfl reduce
//   x_recon        : fused coalesced gather from precomputed 21x1024 table
//   x loads        : register-prefetched one chunk ahead (hidden behind MMA)
// ---------------------------------------------------------------------------

#define NCODES 21
#define LDIM   100
#define IDIM   1024
#define NPAD   128
#define CTA_M  128
#define KC     64
#define NCHUNK (IDIM / KC)
#define NT     16

#define ASCALE 256.0f                 // 2^8
#define BSCALE 1024.0f                // 2^10
#define INVS   3.814697265625e-06f    // 2^-18

__device__ __half g_Bh[NPAD * IDIM];
__device__ __half g_Bl[NPAD * IDIM];
__device__ float  g_recon[NCODES * IDIM];
__device__ float  g_ck[NCODES];            // ||c_k||^2 - 2 b.c_k
__device__ double g_loss;

__device__ __forceinline__ uint32_t smem_u32(const void* p) {
    uint32_t a;
    asm("{ .reg .u64 t; cvta.to.shared.u64 t, %1; cvt.u32.u64 %0, t; }"
        : "=r"(a) : "l"(p));
    return a;
}
__device__ __forceinline__ uint32_t pack_f16x2(float a, float b) {
    uint32_t r;   // low 16 = a, high 16 = b
    asm("cvt.rn.f16x2.f32 %0, %1, %2;" : "=r"(r) : "f"(b), "f"(a));
    return r;
}
__device__ __forceinline__ float2 unpack_h2(uint32_t p) {
    __half2 h = *reinterpret_cast<__half2*>(&p);
    return __half22float2(h);
}
__device__ __forceinline__ uint32_t swz(uint32_t o) { return o ^ ((o >> 3) & 0x70u); }

__device__ __forceinline__ void ldsm_x4(uint32_t* r, uint32_t addr) {
    asm volatile("ldmatrix.sync.aligned.m8n8.x4.shared.b16 {%0,%1,%2,%3}, [%4];"
                 : "=r"(r[0]), "=r"(r[1]), "=r"(r[2]), "=r"(r[3]) : "r"(addr));
}
__device__ __forceinline__ void mma_f16(float* d, const uint32_t* a, const uint32_t* b) {
    asm volatile("mma.sync.aligned.m16n8k16.row.col.f32.f16.f16.f32 "
                 "{%0,%1,%2,%3}, {%4,%5,%6,%7}, {%8,%9}, {%0,%1,%2,%3};"
                 : "+f"(d[0]), "+f"(d[1]), "+f"(d[2]), "+f"(d[3])
                 : "r"(a[0]), "r"(a[1]), "r"(a[2]), "r"(a[3]),
                   "r"(b[0]), "r"(b[1]));
}

// ---------------- smem layout (byte offsets from 128-aligned base) ----------
#define OFF_AH   0
#define OFF_AL   16384
#define OFF_BH   32768
#define OFF_BL   49152          // only 32 rows (tiles 12..15) -> 4 KB
#define OFF_BES  53248
#define OFF_CK   53760
#define OFF_SIDX 53888
#define OFF_LOSS 54400
#define SMEM_BYTES (54416 + 128)

// ---------------------------------------------------------------------------
// K0: setup — extended B (W_enc rows + cb@W_enc rows) scaled fp16 split,
//             recon table, ck consts, loss reset
// ---------------------------------------------------------------------------
__global__ void vq_setup_kernel(const float* __restrict__ W_enc,
                                const float* __restrict__ b_enc,
                                const float* __restrict__ codebook,
                                const float* __restrict__ W_dec,
                                const float* __restrict__ b_dec) {
    int g = blockIdx.x * 256 + threadIdx.x;            // 0 .. 131071
    {
        int n = g >> 10, k = g & 1023;
        float w = 0.f;
        if (n < LDIM) {
            w = W_enc[n * IDIM + k];
        } else if (n < LDIM + NCODES) {
            const float* cb = codebook + (n - LDIM) * LDIM;
#pragma unroll 20
            for (int j = 0; j < LDIM; ++j) w += cb[j] * W_enc[j * IDIM + k];
        }
        float ws = w * BSCALE;
        __half h = __float2half_rn(ws);
        g_Bh[g] = h;
        g_Bl[g] = __float2half_rn(ws - __half2float(h));
    }
    if (g < NCODES * IDIM) {
        int k = g >> 10, d = g & 1023;
        const float4* c4 = (const float4*)(codebook + k * LDIM);
        const float4* w4 = (const float4*)(W_dec + (size_t)d * LDIM);
        float s = b_dec[d];
#pragma unroll
        for (int j = 0; j < LDIM / 4; ++j) {
            float4 a = c4[j], b = w4[j];
            s += a.x * b.x + a.y * b.y + a.z * b.z + a.w * b.w;
        }
        g_recon[g] = s;
    }
    if (g < NCODES) {
        const float* c = codebook + g * LDIM;
        float cn = 0.f, bk = 0.f;
#pragma unroll 10
        for (int j = 0; j < LDIM; ++j) { cn += c[j] * c[j]; bk += b_enc[j] * c[j]; }
        g_ck[g] = cn - 2.f * bk;
    }
    if (g == 0) g_loss = 0.0;
}

// ---------------------------------------------------------------------------
// K1: main — HMMA scaled-fp16-split GEMM + fused argmin/loss/recon
// ---------------------------------------------------------------------------
extern __shared__ __align__(16) char dsm_raw[];

__global__ __launch_bounds__(256, 2)
void vq_main_kernel(const float* __restrict__ x,
                    const float* __restrict__ b_enc,
                    float* __restrict__ out_recon,
                    float* __restrict__ out_idx) {
    const int t = threadIdx.x;
    const int w = t >> 5, L = t & 31;
    const int row0 = blockIdx.x * CTA_M;

    uint32_t raw  = smem_u32(dsm_raw);
    uint32_t base = (raw + 127u) & ~127u;
    char* sm = dsm_raw + (base - raw);

    char* Ah = sm + OFF_AH;  char* Al = sm + OFF_AL;
    char* Bh = sm + OFF_BH;  char* Bl = sm + OFF_BL;
    float* bes   = (float*)(sm + OFF_BES);
    float* cks   = (float*)(sm + OFF_CK);
    int*   sidx  = (int*)  (sm + OFF_SIDX);
    float* sloss = (float*)(sm + OFF_LOSS);

    if (t < LDIM)   bes[t] = b_enc[t];
    if (t < NCODES) cks[t] = g_ck[t];
    if (t == 0)     *sloss = 0.f;

    float acc[NT][4];
#pragma unroll
    for (int j = 0; j < NT; ++j)
#pragma unroll
        for (int e = 0; e < 4; ++e) acc[j][e] = 0.f;

    const uint32_t mask  = (uint32_t)(L & 7) << 4;
    const uint32_t lowA0 = ((uint32_t)(L & 7) << 7) + ((uint32_t)(L >> 4) << 4);
    const uint32_t lowB4 = ((uint32_t)(L & 7) << 7) + ((uint32_t)((L >> 3) & 1) << 4)
                         + ((uint32_t)(L >> 4) << 10);
    const uint32_t aRow  = ((uint32_t)(w * 2 + ((L >> 3) & 1))) << 10;
    const uint32_t AhB = base + OFF_AH + aRow;
    const uint32_t AlB = base + OFF_AL + aRow;
    const uint32_t BhB = base + OFF_BH;
    const uint32_t BlB = base + OFF_BL - (12 << 10);   // tile j>=12 rebased

    // per-thread source coords
    const int xr = (t >> 4);          // row % 16 group
    const int xc = (t & 15) * 4;      // k offset (4 floats)

    // ---- prefetch chunk 0 of x into registers
    float4 xv[8];
#pragma unroll
    for (int it = 0; it < 8; ++it)
        xv[it] = *(const float4*)(x + (size_t)(row0 + it * 16 + xr) * IDIM + xc);

    for (int ch = 0; ch < NCHUNK; ++ch) {
        const int kc = ch * KC;
        __syncthreads();
        // ---- convert prefetched A: scaled (hi,lo) fp16 RN split, SW128 tiles
#pragma unroll
        for (int it = 0; it < 8; ++it) {
            float4 v = xv[it];
            int row = it * 16 + xr;
            float sx = v.x * ASCALE, sy = v.y * ASCALE;
            float sz = v.z * ASCALE, sw = v.w * ASCALE;
            uint32_t h01 = pack_f16x2(sx, sy);
            uint32_t h23 = pack_f16x2(sz, sw);
            float2 b01 = unpack_h2(h01), b23 = unpack_h2(h23);
            uint32_t l01 = pack_f16x2(sx - b01.x, sy - b01.y);
            uint32_t l23 = pack_f16x2(sz - b23.x, sw - b23.y);
            uint32_t off = swz((uint32_t)(row * 128 + xc * 2));
            *(uint2*)(Ah + off) = make_uint2(h01, h23);
            *(uint2*)(Al + off) = make_uint2(l01, l23);
        }
        // ---- stage Bh (128 rows) + Bl (rows 96..127 only), L2-hot
#pragma unroll
        for (int it = 0; it < 4; ++it) {
            int idx = it * 256 + t;                 // 0..1023
            int n = idx >> 3, k8 = (idx & 7) * 8;
            uint32_t off = swz((uint32_t)(n * 128 + k8 * 2));
            *(uint4*)(Bh + off) = *(const uint4*)(g_Bh + (size_t)n * IDIM + kc + k8);
        }
        {
            int n = t >> 3, k8 = (t & 7) * 8;       // n = 0..31
            uint32_t off = swz((uint32_t)(n * 128 + k8 * 2));
            *(uint4*)(Bl + off) = *(const uint4*)(g_Bl + (size_t)(96 + n) * IDIM + kc + k8);
        }
        __syncthreads();

        // ---- prefetch next chunk's x (latency hidden behind MMA below)
        if (ch + 1 < NCHUNK) {
            const float* xn = x + kc + KC + xc;
#pragma unroll
            for (int it = 0; it < 8; ++it)
                xv[it] = *(const float4*)(xn + (size_t)(row0 + it * 16 + xr) * IDIM);
        }

#pragma unroll
        for (int ks = 0; ks < 4; ++ks) {
            const uint32_t aoff = (lowA0 + (ks << 5)) ^ mask;
            const uint32_t boff = (lowB4 + (ks << 5)) ^ mask;
            uint32_t ah[4], al[4];
            ldsm_x4(ah, AhB + aoff);
            ldsm_x4(al, AlB + aoff);
#pragma unroll
            for (int j = 0; j < 12; j += 2) {       // z tiles: hh + lh
                uint32_t bh[4];
                ldsm_x4(bh, BhB + boff + (j << 10));
                mma_f16(acc[j],     ah, bh);
                mma_f16(acc[j],     al, bh);
                mma_f16(acc[j + 1], ah, bh + 2);
                mma_f16(acc[j + 1], al, bh + 2);
            }
#pragma unroll
            for (int j = 12; j < 16; j += 2) {      // dot tiles: hh + lh + hl
                uint32_t bh[4], bl[4];
                ldsm_x4(bh, BhB + boff + (j << 10));
                ldsm_x4(bl, BlB + boff + (j << 10));
                mma_f16(acc[j],     ah, bh);
                mma_f16(acc[j],     al, bh);
                mma_f16(acc[j],     ah, bl);
                mma_f16(acc[j + 1], ah, bh + 2);
                mma_f16(acc[j + 1], al, bh + 2);
                mma_f16(acc[j + 1], ah, bl + 2);
            }
        }
    }

    // ---- epilogue (registers only). Thread owns rows (w*16+q, +8),
    //      cols 8j + 2*c0 + e, with c0 = L&3, q = L>>2. acc scaled by 2^18.
    const int c0 = L & 3;
    float zz0 = 0.f, zz1 = 0.f;
#pragma unroll
    for (int j = 0; j < 13; ++j) {
#pragma unroll
        for (int e = 0; e < 2; ++e) {
            int col = 8 * j + 2 * c0 + e;
            if (col < LDIM) {
                float b = bes[col];
                float z0 = fmaf(acc[j][e],     INVS, b);  zz0 += z0 * z0;
                float z1 = fmaf(acc[j][e + 2], INVS, b);  zz1 += z1 * z1;
            }
        }
    }
    float bd0 = 3.4e38f, bd1 = 3.4e38f;
    int   bk0 = NCODES,  bk1 = NCODES;
#pragma unroll
    for (int j = 12; j < NT; ++j) {
#pragma unroll
        for (int e = 0; e < 2; ++e) {
            int col = 8 * j + 2 * c0 + e;
            int k = col - LDIM;
            if (k >= 0 && k < NCODES) {
                float ckv = cks[k];
                float s0 = fmaf(acc[j][e],     -2.f * INVS, ckv);
                float s1 = fmaf(acc[j][e + 2], -2.f * INVS, ckv);
                if (s0 < bd0) { bd0 = s0; bk0 = k; }
                if (s1 < bd1) { bd1 = s1; bk1 = k; }
            }
        }
    }
#pragma unroll
    for (int off = 1; off < 4; off <<= 1) {
        float od0 = __shfl_xor_sync(0xffffffffu, bd0, off);
        int   ok0 = __shfl_xor_sync(0xffffffffu, bk0, off);
        float od1 = __shfl_xor_sync(0xffffffffu, bd1, off);
        int   ok1 = __shfl_xor_sync(0xffffffffu, bk1, off);
        zz0 += __shfl_xor_sync(0xffffffffu, zz0, off);
        zz1 += __shfl_xor_sync(0xffffffffu, zz1, off);
        if (od0 < bd0 || (od0 == bd0 && ok0 < bk0)) { bd0 = od0; bk0 = ok0; }
        if (od1 < bd1 || (od1 == bd1 && ok1 < bk1)) { bd1 = od1; bk1 = ok1; }
    }
    if (c0 == 0) {
        int q  = L >> 2;
        int r0 = w * 16 + q, r1 = r0 + 8;
        sidx[r0] = bk0;  sidx[r1] = bk1;
        out_idx[row0 + r0] = (float)bk0;
        out_idx[row0 + r1] = (float)bk1;
        atomicAdd(sloss, (zz0 + bd0) + (zz1 + bd1));
    }
    __syncthreads();
    if (t == 0) atomicAdd(&g_loss, (double)*sloss);

    // ---- fused recon gather (table L2-resident)
#pragma unroll 4
    for (int r = 0; r < CTA_M; ++r) {
        int k = sidx[r];
        float4 v = *(const float4*)(g_recon + (size_t)k * IDIM + t * 4);
        *(float4*)(out_recon + (size_t)(row0 + r) * IDIM + t * 4) = v;
    }
}

// ---------------------------------------------------------------------------
// K2: finalize loss
// ---------------------------------------------------------------------------
__global__ void vq_fin_kernel(float* __restrict__ out_loss, int M) {
    out_loss[0] = (float)(1.1 * g_loss / ((double)M * (double)LDIM));
}

extern "C" void kernel_launch(void* const* d_in, const int* in_sizes, int n_in,
                              void* d_out, int out_size) {
    const float* x        = (const float*)d_in[0];
    const float* W_enc    = (const float*)d_in[1];
    const float* b_enc    = (const float*)d_in[2];
    const float* codebook = (const float*)d_in[3];
    const float* W_dec    = (const float*)d_in[4];
    const float* b_dec    = (const float*)d_in[5];
    float* out = (float*)d_out;

    const int M = in_sizes[0] / IDIM;           // 65536
    float* out_recon = out;
    float* out_loss  = out + (size_t)M * IDIM;
    float* out_idx   = out_loss + 1;

    cudaFuncSetAttribute(vq_main_kernel,
                         cudaFuncAttributeMaxDynamicSharedMemorySize, SMEM_BYTES);

    vq_setup_kernel<<<(NPAD * IDIM) / 256, 256>>>(W_enc, b_enc, codebook, W_dec, b_dec);
    vq_main_kernel<<<M / CTA_M, 256, SMEM_BYTES>>>(x, b_enc, out_recon, out_idx);
    vq_fin_kernel<<<1, 1>>>(out_loss, M);
}